// round 13
// baseline (speedup 1.0000x reference)
#include <cuda_runtime.h>
#include <cuda_fp16.h>
#include <math.h>
#include <stdint.h>

#define N_NODES 12000
#define F 35
#define FP 36
#define QPAD 12032
#define NSPLIT 3
#define KT 64
#define NTILES 188          // 188 * 64 = 12032 padded keys
#define E_EDGES 192000
#define B_GRAPHS 64
#define H1 1500
#define H2 128

// ---------------- scratch ----------------
__device__ __align__(16) uint32_t d_Kn32[QPAD * 24];  // queries f16 [row][48]
__device__ __align__(16) uint32_t d_Qk32[QPAD * 24];  // keys f16
__device__ __align__(16) __half d_VtT[40 * QPAD];     // V^T f16; row35=ones, pad cols=0
__device__ float d_Vex[QPAD * 40];
__device__ float d_Opart[NSPLIT][QPAD * 40];
__device__ float4 d_h4[N_NODES * 9];    // h, 36-stride; elem35 = 1.0 (deg carrier)
__device__ float4 d_agg4[N_NODES * 9];  // agg; elem35 accumulates degree
__device__ float d_Weff[F * F];
__device__ float d_beff[F];
__device__ float d_Wc[F * F];
__device__ float d_bc[F];
__device__ float d_g[B_GRAPHS * FP];
__device__ float d_g1[B_GRAPHS * H1];
__device__ float d_g2[B_GRAPHS * H2];
__device__ int d_is64;

// pack two f32 into f16x2 (hi -> upper half)
__device__ __forceinline__ uint32_t packh(float hi, float lo) {
    uint32_t r;
    asm("cvt.rn.f16x2.f32 %0, %1, %2;" : "=r"(r) : "f"(hi), "f"(lo));
    return r;
}
// packed 2-wide exp2 on f16x2
__device__ __forceinline__ uint32_t ex2h2(uint32_t x) {
    uint32_t r;
    asm("ex2.approx.f16x2 %0, %1;" : "=r"(r) : "r"(x));
    return r;
}
#define MMA_F16(d0, d1, d2, d3, a0, a1, a2, a3, b0, b1)                                    \
    asm volatile(                                                                          \
        "mma.sync.aligned.m16n8k16.row.col.f32.f16.f16.f32 "                               \
        "{%0,%1,%2,%3},{%4,%5,%6,%7},{%8,%9},{%0,%1,%2,%3};"                               \
        : "+f"(d0), "+f"(d1), "+f"(d2), "+f"(d3)                                           \
        : "r"(a0), "r"(a1), "r"(a2), "r"(a3), "r"(b0), "r"(b1))
#define CPA16(dst, src) \
    asm volatile("cp.async.cg.shared.global [%0], [%1], 16;" :: "r"(dst), "l"(src))
#define CPA_COMMIT() asm volatile("cp.async.commit_group;")
#define CPA_WAIT1()  asm volatile("cp.async.wait_group 1;")

__device__ __forceinline__ void red4(float4* p, float4 v) {
    asm volatile("red.global.add.v4.f32 [%0], {%1,%2,%3,%4};"
                 :: "l"(p), "f"(v.x), "f"(v.y), "f"(v.z), "f"(v.w) : "memory");
}

// ---------------- setup: detect + pre1 + pre2 (block 0), zero (blocks 1+) ----------------
__global__ void setup_kernel(const int* __restrict__ ei,
                             const float* __restrict__ Wl, const float* __restrict__ W3,
                             const float* __restrict__ W5, const float* __restrict__ b3,
                             const float* __restrict__ b5, const float* __restrict__ bl,
                             const float* __restrict__ Wk, const float* __restrict__ bk) {
    int tid = threadIdx.x;
    if (blockIdx.x == 0) {
        if (tid == 0) {
            int all0 = 1;
            for (int i = 0; i < 16; i++)
                if (ei[2 * i + 1] != 0) all0 = 0;
            d_is64 = all0;
        }
        for (int idx = tid; idx < F * 36; idx += 256) {
            int o = idx / 36, k = idx % 36;
            if (k < F) {
                float w = Wl[o * 105 + 70 + k];
                for (int m = 0; m < F; m++) {
                    w = fmaf(Wl[o * 105 + m],      W3[(m * F + k) * 3 + 1], w);
                    w = fmaf(Wl[o * 105 + 35 + m], W5[(m * F + k) * 5 + 2], w);
                }
                d_Weff[o * F + k] = w;
            } else {
                float be = bl[o];
                for (int m = 0; m < F; m++) {
                    be = fmaf(Wl[o * 105 + m],      b3[m], be);
                    be = fmaf(Wl[o * 105 + 35 + m], b5[m], be);
                }
                d_beff[o] = be;
            }
        }
        __syncthreads();
        const float CS = 1.4426950408889634f / sqrtf((float)F);
        for (int idx = tid; idx < F * 36; idx += 256) {
            int o = idx / 36, j = idx % 36;
            if (j < F) {
                float w = 0.f;
                for (int k = 0; k < F; k++) w = fmaf(d_Weff[o * F + k], Wk[k * F + j], w);
                d_Wc[o * F + j] = w * CS;
            } else {
                float b = d_beff[o];
                for (int k = 0; k < F; k++) b = fmaf(d_Weff[o * F + k], bk[k], b);
                d_bc[o] = b * CS;
            }
        }
    } else {
        int i = (blockIdx.x - 1) * 256 + tid;
        int stride = (gridDim.x - 1) * 256;
        float* af = (float*)d_agg4;
        for (int k = i; k < N_NODES * FP; k += stride) af[k] = 0.f;
        for (int k = i; k < B_GRAPHS * FP; k += stride) d_g[k] = 0.f;
    }
}

// ---------------- proj: 32 nodes/block, 8 threads/node x 14 outputs ----------------
__global__ __launch_bounds__(256) void proj_kernel(const float* __restrict__ x,
                                                   const float* __restrict__ Wq,
                                                   const float* __restrict__ bq,
                                                   const float* __restrict__ Wv,
                                                   const float* __restrict__ bv) {
    __shared__ __align__(16) float Wall[112 * 36];
    __shared__ float bsh[112];
    __shared__ __align__(16) float4 xs4[9][32];
    __shared__ float outS[32 * 113];
    int tid = threadIdx.x;
    int node0 = blockIdx.x * 32;

    for (int idx = tid; idx < 112 * 36; idx += 256) {
        int o = idx / 36, j = idx % 36;
        float v = 0.f;
        if (j < F && o < 105) {
            if (o < 35)      v = Wq[o * 35 + j];
            else if (o < 70) v = Wv[(o - 35) * 35 + j];
            else             v = d_Wc[(o - 70) * 35 + j];
        }
        Wall[idx] = v;
    }
    if (tid < 112) {
        float b = 0.f;
        if (tid < 35)       b = bq[tid];
        else if (tid < 70)  b = bv[tid - 35];
        else if (tid < 105) b = d_bc[tid - 70];
        bsh[tid] = b;
    }
    {
        float* xsf = (float*)xs4;
        for (int idx = tid; idx < 32 * 35; idx += 256) {
            int n = idx / 35, j = idx % 35;
            float v = (node0 + n < N_NODES) ? x[node0 * 35 + idx] : 0.f;
            xsf[(j >> 2) * 128 + n * 4 + (j & 3)] = v;
        }
        if (tid < 32) xsf[8 * 128 + tid * 4 + 3] = 0.f;
    }
    __syncthreads();

    int c = tid >> 5;
    int n = tid & 31;
    float4 xv[9];
#pragma unroll
    for (int j4 = 0; j4 < 9; j4++) xv[j4] = xs4[j4][n];
    int o0 = c * 14;
    float acc[14];
#pragma unroll
    for (int k = 0; k < 14; k++) acc[k] = bsh[o0 + k];
#pragma unroll
    for (int j4 = 0; j4 < 9; j4++) {
        float4 xq = xv[j4];
#pragma unroll
        for (int k = 0; k < 14; k++) {
            const float4 wv = *(const float4*)&Wall[(o0 + k) * 36 + j4 * 4];
            acc[k] = fmaf(wv.x, xq.x, acc[k]);
            acc[k] = fmaf(wv.y, xq.y, acc[k]);
            acc[k] = fmaf(wv.z, xq.z, acc[k]);
            acc[k] = fmaf(wv.w, xq.w, acc[k]);
        }
    }
#pragma unroll
    for (int k = 0; k < 14; k++) outS[n * 113 + o0 + k] = acc[k];
    __syncthreads();

    // Kn f16 (queries); pad nodes -> 0
    for (int idx = tid; idx < 32 * 24; idx += 256) {
        int nn = idx / 24, wd = idx % 24;
        int real = (node0 + nn < N_NODES);
        int f0 = 2 * wd;
        float v0 = (real && f0 < 35)     ? outS[nn * 113 + 70 + f0]     : 0.f;
        float v1 = (real && f0 + 1 < 35) ? outS[nn * 113 + 70 + f0 + 1] : 0.f;
        d_Kn32[(node0 + nn) * 24 + wd] = packh(v1, v0);
    }
    // Qk f16 (keys); pad -> 0
    for (int idx = tid; idx < 32 * 24; idx += 256) {
        int nn = idx / 24, wd = idx % 24;
        int real = (node0 + nn < N_NODES);
        int f0 = 2 * wd;
        float v0 = (real && f0 < 35)     ? outS[nn * 113 + f0]     : 0.f;
        float v1 = (real && f0 + 1 < 35) ? outS[nn * 113 + f0 + 1] : 0.f;
        d_Qk32[(node0 + nn) * 24 + wd] = packh(v1, v0);
    }
    // V^T f16; row 35 = ones for real nodes, 0 for pad (kills pad-key contributions)
    for (int idx = tid; idx < 36 * 32; idx += 256) {
        int f = idx >> 5, nn = idx & 31;
        int real = (node0 + nn < N_NODES);
        float v = real ? ((f < 35) ? outS[nn * 113 + 35 + f] : 1.0f) : 0.f;
        d_VtT[f * QPAD + node0 + nn] = __float2half(v);
    }
    // Vex exact f32
    for (int idx = tid; idx < 32 * 40; idx += 256) {
        int nn = idx / 40, f = idx % 40;
        int real = (node0 + nn < N_NODES);
        d_Vex[(node0 + nn) * 40 + f] = (real && f < 35) ? outS[nn * 113 + 35 + f] : 0.f;
    }
}

// ---------------- f16 flash attention: 256 q/CTA, 32 q/warp, 64-key tiles ----------------
// K/V fragments feed both query halves; P = ex2.approx.f16x2 straight into A-fragments.
__global__ __launch_bounds__(256) void attn_kernel() {
    __shared__ __align__(16) uint32_t Ks[2][KT * 28];  // keys [64][56] f16
    __shared__ __align__(16) uint32_t Vs[2][40 * 36];  // V^T [40][72] f16

    int tid = threadIdx.x;
    int w = tid >> 5, lane = tid & 31;
    int gid = lane >> 2, tig = lane & 3;
    int qbase = blockIdx.x * 256 + w * 32;
    int split = blockIdx.y;
    int t0 = split * 63;
    int tend = (split == 2) ? NTILES : t0 + 63;

    uint32_t A[2][3][4];
#pragma unroll
    for (int h = 0; h < 2; h++)
#pragma unroll
        for (int kc = 0; kc < 3; kc++) {
            int r0 = qbase + h * 16 + gid;
            A[h][kc][0] = d_Kn32[r0 * 24 + 8 * kc + tig];
            A[h][kc][1] = d_Kn32[(r0 + 8) * 24 + 8 * kc + tig];
            A[h][kc][2] = d_Kn32[r0 * 24 + 8 * kc + tig + 4];
            A[h][kc][3] = d_Kn32[(r0 + 8) * 24 + 8 * kc + tig + 4];
        }
    float O[2][5][4];
#pragma unroll
    for (int h = 0; h < 2; h++)
#pragma unroll
        for (int nt = 0; nt < 5; nt++)
#pragma unroll
            for (int r = 0; r < 4; r++) O[h][nt][r] = 0.f;

    uint32_t ksb = (uint32_t)__cvta_generic_to_shared(&Ks[0][0]);
    uint32_t vsb = (uint32_t)__cvta_generic_to_shared(&Vs[0][0]);

    {
        int k0 = t0 * KT;
        for (int i = tid; i < 704; i += 256) {
            if (i < 384) {
                int r = i / 6, ch = i % 6;
                CPA16(ksb + r * 112 + ch * 16,
                      (const char*)d_Qk32 + (size_t)(k0 + r) * 96 + ch * 16);
            } else {
                int j = i - 384; int r = j >> 3, ch = j & 7;
                CPA16(vsb + r * 144 + ch * 16,
                      (const char*)d_VtT + ((size_t)r * QPAD + k0) * 2 + ch * 16);
            }
        }
    }
    CPA_COMMIT();

    for (int t = t0; t < tend; t++) {
        int cur = (t - t0) & 1;
        if (t + 1 < tend) {
            int nb = cur ^ 1;
            int k0 = (t + 1) * KT;
            for (int i = tid; i < 704; i += 256) {
                if (i < 384) {
                    int r = i / 6, ch = i % 6;
                    CPA16(ksb + nb * 7168 + r * 112 + ch * 16,
                          (const char*)d_Qk32 + (size_t)(k0 + r) * 96 + ch * 16);
                } else {
                    int j = i - 384; int r = j >> 3, ch = j & 7;
                    CPA16(vsb + nb * 5760 + r * 144 + ch * 16,
                          (const char*)d_VtT + ((size_t)r * QPAD + k0) * 2 + ch * 16);
                }
            }
        }
        CPA_COMMIT();
        CPA_WAIT1();
        __syncthreads();

        const uint32_t* K_ = Ks[cur];
        const uint32_t* V_ = Vs[cur];

#pragma unroll
        for (int c = 0; c < 2; c++) {
            float S[2][4][4];
#pragma unroll
            for (int h = 0; h < 2; h++)
#pragma unroll
                for (int n4 = 0; n4 < 4; n4++)
#pragma unroll
                    for (int r = 0; r < 4; r++) S[h][n4][r] = 0.f;
            // ---- S chunk: Kn(2x16x48) @ keys^T ----
#pragma unroll
            for (int kc = 0; kc < 3; kc++) {
#pragma unroll
                for (int n4 = 0; n4 < 4; n4++) {
                    int nt = 4 * c + n4;
                    uint32_t b0 = K_[(nt * 8 + gid) * 28 + 8 * kc + tig];
                    uint32_t b1 = K_[(nt * 8 + gid) * 28 + 8 * kc + tig + 4];
                    MMA_F16(S[0][n4][0], S[0][n4][1], S[0][n4][2], S[0][n4][3],
                            A[0][kc][0], A[0][kc][1], A[0][kc][2], A[0][kc][3], b0, b1);
                    MMA_F16(S[1][n4][0], S[1][n4][1], S[1][n4][2], S[1][n4][3],
                            A[1][kc][0], A[1][kc][1], A[1][kc][2], A[1][kc][3], b0, b1);
                }
            }
            // ---- pack to f16x2 + packed exp2 -> P fragments ----
            uint32_t aP[2][2][4];
#pragma unroll
            for (int h = 0; h < 2; h++)
#pragma unroll
                for (int ks = 0; ks < 2; ks++) {
                    aP[h][ks][0] = ex2h2(packh(S[h][2 * ks][1],     S[h][2 * ks][0]));
                    aP[h][ks][1] = ex2h2(packh(S[h][2 * ks][3],     S[h][2 * ks][2]));
                    aP[h][ks][2] = ex2h2(packh(S[h][2 * ks + 1][1], S[h][2 * ks + 1][0]));
                    aP[h][ks][3] = ex2h2(packh(S[h][2 * ks + 1][3], S[h][2 * ks + 1][2]));
                }
            // ---- O += P chunk @ V ----
#pragma unroll
            for (int ks = 0; ks < 2; ks++) {
                int kc = 2 * c + ks;
#pragma unroll
                for (int nt = 0; nt < 5; nt++) {
                    uint32_t b0 = V_[(nt * 8 + gid) * 36 + 8 * kc + tig];
                    uint32_t b1 = V_[(nt * 8 + gid) * 36 + 8 * kc + tig + 4];
                    MMA_F16(O[0][nt][0], O[0][nt][1], O[0][nt][2], O[0][nt][3],
                            aP[0][ks][0], aP[0][ks][1], aP[0][ks][2], aP[0][ks][3], b0, b1);
                    MMA_F16(O[1][nt][0], O[1][nt][1], O[1][nt][2], O[1][nt][3],
                            aP[1][ks][0], aP[1][ks][1], aP[1][ks][2], aP[1][ks][3], b0, b1);
                }
            }
        }
        __syncthreads();
    }

    float* Op = d_Opart[split];
#pragma unroll
    for (int h = 0; h < 2; h++) {
        int q0r = qbase + h * 16 + gid, q1r = q0r + 8;
#pragma unroll
        for (int nt = 0; nt < 5; nt++) {
            *(float2*)&Op[q0r * 40 + nt * 8 + 2 * tig] = make_float2(O[h][nt][0], O[h][nt][1]);
            *(float2*)&Op[q1r * 40 + nt * 8 + 2 * tig] = make_float2(O[h][nt][2], O[h][nt][3]);
        }
    }
}

// ---------------- merge: h = relu(O/l + V); elem 35 = 1.0 (degree carrier) ----------------
__global__ void merge_kernel() {
    int i = blockIdx.x * blockDim.x + threadIdx.x;
    if (i >= N_NODES * FP) return;
    int q = i / FP, f = i - q * FP;
    float r;
    if (f == 35) {
        r = 1.0f;
    } else {
        float O = d_Opart[0][q * 40 + f] + d_Opart[1][q * 40 + f] + d_Opart[2][q * 40 + f];
        float l = d_Opart[0][q * 40 + 35] + d_Opart[1][q * 40 + 35] + d_Opart[2][q * 40 + 35];
        float v = d_Vex[q * 40 + f];
        r = fmaxf(fmaf(O, 1.0f / l, v), 0.f);
    }
    ((float*)d_h4)[i] = r;
}

// ---------------- SAGE scatter: thread-per-edge, v4 reductions (deg rides elem 35) ----------------
__global__ void scatter_kernel(const int* __restrict__ ei) {
    int e = blockIdx.x * blockDim.x + threadIdx.x;
    if (e >= E_EDGES) return;
    int is64 = d_is64;
    int src = is64 ? ei[2 * e] : ei[e];
    int dst = is64 ? ei[2 * (E_EDGES + e)] : ei[E_EDGES + e];
    const float4* hs = d_h4 + src * 9;
    float4* ag = d_agg4 + dst * 9;
#pragma unroll
    for (int i = 0; i < 9; i++) red4(ag + i, hs[i]);
}

// ---------------- SAGE combine + fused global max pool ----------------
__global__ __launch_bounds__(128) void sage_kernel(const float* __restrict__ Wll,
                                                   const float* __restrict__ bll,
                                                   const float* __restrict__ Wlr,
                                                   const int* __restrict__ bat) {
    __shared__ float Wl_s[F * F], Wr_s[F * F], bl_s[F];
    __shared__ float hs[F][33], as[F][33];
    __shared__ float rd[32];
    __shared__ int bs[32];
    int tid = threadIdx.x;
    int n0 = blockIdx.x * 32;
    int is64 = d_is64;
    const float* hf = (const float*)d_h4;
    const float* af = (const float*)d_agg4;
    for (int w = tid; w < F * F; w += 128) {
        Wl_s[w] = Wll[w];
        Wr_s[w] = Wlr[w];
    }
    if (tid < F) bl_s[tid] = bll[tid];
    if (tid < 32) {
        rd[tid] = 1.0f / fmaxf(af[(n0 + tid) * FP + 35], 1.0f);
        int node = n0 + tid;
        bs[tid] = is64 ? bat[2 * node] : bat[node];
    }
    for (int w = tid; w < 32 * F; w += 128) {
        int n = w / F, j = w % F;
        hs[j][n] = hf[(n0 + n) * FP + j];
        as[j][n] = af[(n0 + n) * FP + j];
    }
    __syncthreads();
    for (int w = tid; w < 32 * F; w += 128) {
        int n = w & 31, o = w >> 5;
        float a1 = 0.f, a2 = 0.f;
#pragma unroll
        for (int j = 0; j < F; j++) {
            a1 = fmaf(as[j][n], Wl_s[o * F + j], a1);
            a2 = fmaf(hs[j][n], Wr_s[o * F + j], a2);
        }
        float r = fmaf(a1, rd[n], bl_s[o]) + a2;
        r = fmaxf(r, 0.f);
        atomicMax((int*)&d_g[bs[n] * FP + o], __float_as_int(r));
    }
}

// ---------------- MLP head ----------------
__global__ __launch_bounds__(128) void mlp1_kernel(const float* __restrict__ Wg1,
                                                   const float* __restrict__ bg1) {
    __shared__ float gs[F][64];
    int tid = threadIdx.x;
    for (int w = tid; w < 64 * F; w += 128) {
        int b = w / F, d = w % F;
        gs[d][b] = d_g[b * FP + d];
    }
    __syncthreads();
    int j = blockIdx.x * 2 + (tid >> 6);
    int b = tid & 63;
    float acc = 0.f;
#pragma unroll
    for (int d = 0; d < F; d++) acc = fmaf(gs[d][b], __ldg(&Wg1[j * F + d]), acc);
    d_g1[b * H1 + j] = fmaxf(acc + bg1[j], 0.f);
}

__global__ void mlp2_kernel(const float* __restrict__ Wg2, const float* __restrict__ bg2) {
    int wid = (blockIdx.x * blockDim.x + threadIdx.x) >> 5;
    int lane = threadIdx.x & 31;
    if (wid >= B_GRAPHS * H2) return;
    int b = wid >> 7, j = wid & 127;
    float acc = 0.f;
    for (int d = lane; d < H1; d += 32)
        acc = fmaf(d_g1[b * H1 + d], Wg2[j * H1 + d], acc);
#pragma unroll
    for (int off = 16; off; off >>= 1) acc += __shfl_xor_sync(0xffffffffu, acc, off);
    if (lane == 0) d_g2[b * H2 + j] = acc + bg2[j];
}

__global__ void out_kernel(const float* __restrict__ Wo, const float* __restrict__ bo,
                           float* __restrict__ out) {
    int b = threadIdx.x;
    if (b < B_GRAPHS) {
        float acc = 0.f;
#pragma unroll
        for (int d = 0; d < H2; d++) acc = fmaf(d_g2[b * H2 + d], Wo[d], acc);
        out[b] = acc + bo[0];
    }
}

extern "C" void kernel_launch(void* const* d_in, const int* in_sizes, int n_in,
                              void* d_out, int out_size) {
    const float* x   = (const float*)d_in[0];
    const int*   ei  = (const int*)d_in[1];
    const int*   bat = (const int*)d_in[2];
    const float* Wq  = (const float*)d_in[3];
    const float* bq  = (const float*)d_in[4];
    const float* Wk  = (const float*)d_in[5];
    const float* bk  = (const float*)d_in[6];
    const float* Wv  = (const float*)d_in[7];
    const float* bv  = (const float*)d_in[8];
    const float* W3  = (const float*)d_in[9];
    const float* b3  = (const float*)d_in[10];
    const float* W5  = (const float*)d_in[11];
    const float* b5  = (const float*)d_in[12];
    const float* Wl  = (const float*)d_in[13];
    const float* bl  = (const float*)d_in[14];
    const float* Wll = (const float*)d_in[15];
    const float* bll = (const float*)d_in[16];
    const float* Wlr = (const float*)d_in[17];
    const float* Wg1 = (const float*)d_in[18];
    const float* bg1 = (const float*)d_in[19];
    const float* Wg2 = (const float*)d_in[20];
    const float* bg2 = (const float*)d_in[21];
    const float* Wo  = (const float*)d_in[22];
    const float* bo  = (const float*)d_in[23];
    float* out = (float*)d_out;

    setup_kernel<<<64, 256>>>(ei, Wl, W3, W5, b3, b5, bl, Wk, bk);
    proj_kernel<<<QPAD / 32, 256>>>(x, Wq, bq, Wv, bv);
    attn_kernel<<<dim3(47, NSPLIT), 256>>>();
    merge_kernel<<<(N_NODES * FP + 255) / 256, 256>>>();
    scatter_kernel<<<(E_EDGES + 255) / 256, 256>>>(ei);
    sage_kernel<<<N_NODES / 32, 128>>>(Wll, bll, Wlr, bat);
    mlp1_kernel<<<H1 / 2, 128>>>(Wg1, bg1);
    mlp2_kernel<<<B_GRAPHS * H2 / 4, 128>>>(Wg2, bg2);
    out_kernel<<<1, 64>>>(Wo, bo, out);
}

// round 14
// speedup vs baseline: 1.1099x; 1.1099x over previous
#include <cuda_runtime.h>
#include <cuda_bf16.h>
#include <math.h>
#include <stdint.h>

#define N_NODES 12000
#define F 35
#define FP 36
#define QPAD 12032
#define NSPLIT 6
#define SPLIT_TILES 32
#define KT 64
#define NTILES 188          // 188 * 64 = 12032 padded keys
#define E_EDGES 192000
#define B_GRAPHS 64
#define H1 1500
#define H2 128

// ---------------- scratch ----------------
__device__ __align__(16) uint32_t d_Kn32[QPAD * 24];  // queries bf16 [row][48]
__device__ __align__(16) uint32_t d_Qk32[QPAD * 24];  // keys bf16
__device__ __align__(16) uint16_t d_VtT[40 * QPAD];   // V^T bf16; row35=ones, pad cols=0
__device__ float d_Vex[QPAD * 40];
__device__ float d_Opart[NSPLIT][QPAD * 40];
__device__ float4 d_h4[N_NODES * 9];    // h, 36-stride; elem35 = 1.0 (deg carrier)
__device__ float4 d_agg4[N_NODES * 9];  // agg; elem35 accumulates degree
__device__ float d_Weff[F * F];
__device__ float d_beff[F];
__device__ float d_Wc[F * F];
__device__ float d_bc[F];
__device__ float d_g[B_GRAPHS * FP];
__device__ float d_g1[B_GRAPHS * H1];
__device__ float d_g2[B_GRAPHS * H2];
__device__ int d_is64;

__device__ __forceinline__ float ex2f(float x) {
    float r;
    asm("ex2.approx.f32 %0, %1;" : "=f"(r) : "f"(x));
    return r;
}
__device__ __forceinline__ uint32_t packbf(float hi, float lo) {
    uint32_t r;
    asm("cvt.rn.bf16x2.f32 %0, %1, %2;" : "=r"(r) : "f"(hi), "f"(lo));
    return r;
}
#define MMA_BF16(d0, d1, d2, d3, a0, a1, a2, a3, b0, b1)                                   \
    asm volatile(                                                                          \
        "mma.sync.aligned.m16n8k16.row.col.f32.bf16.bf16.f32 "                             \
        "{%0,%1,%2,%3},{%4,%5,%6,%7},{%8,%9},{%0,%1,%2,%3};"                               \
        : "+f"(d0), "+f"(d1), "+f"(d2), "+f"(d3)                                           \
        : "r"(a0), "r"(a1), "r"(a2), "r"(a3), "r"(b0), "r"(b1))
#define CPA16(dst, src) \
    asm volatile("cp.async.cg.shared.global [%0], [%1], 16;" :: "r"(dst), "l"(src))
#define CPA_COMMIT() asm volatile("cp.async.commit_group;")
#define CPA_WAIT1()  asm volatile("cp.async.wait_group 1;")

__device__ __forceinline__ void red4(float4* p, float4 v) {
    asm volatile("red.global.add.v4.f32 [%0], {%1,%2,%3,%4};"
                 :: "l"(p), "f"(v.x), "f"(v.y), "f"(v.z), "f"(v.w) : "memory");
}

// ---------------- setup: detect + pre1 + pre2 (block 0), zero (blocks 1+) ----------------
__global__ void setup_kernel(const int* __restrict__ ei,
                             const float* __restrict__ Wl, const float* __restrict__ W3,
                             const float* __restrict__ W5, const float* __restrict__ b3,
                             const float* __restrict__ b5, const float* __restrict__ bl,
                             const float* __restrict__ Wk, const float* __restrict__ bk) {
    int tid = threadIdx.x;
    if (blockIdx.x == 0) {
        if (tid == 0) {
            int all0 = 1;
            for (int i = 0; i < 16; i++)
                if (ei[2 * i + 1] != 0) all0 = 0;
            d_is64 = all0;
        }
        for (int idx = tid; idx < F * 36; idx += 256) {
            int o = idx / 36, k = idx % 36;
            if (k < F) {
                float w = Wl[o * 105 + 70 + k];
                for (int m = 0; m < F; m++) {
                    w = fmaf(Wl[o * 105 + m],      W3[(m * F + k) * 3 + 1], w);
                    w = fmaf(Wl[o * 105 + 35 + m], W5[(m * F + k) * 5 + 2], w);
                }
                d_Weff[o * F + k] = w;
            } else {
                float be = bl[o];
                for (int m = 0; m < F; m++) {
                    be = fmaf(Wl[o * 105 + m],      b3[m], be);
                    be = fmaf(Wl[o * 105 + 35 + m], b5[m], be);
                }
                d_beff[o] = be;
            }
        }
        __syncthreads();
        const float CS = 1.4426950408889634f / sqrtf((float)F);
        for (int idx = tid; idx < F * 36; idx += 256) {
            int o = idx / 36, j = idx % 36;
            if (j < F) {
                float w = 0.f;
                for (int k = 0; k < F; k++) w = fmaf(d_Weff[o * F + k], Wk[k * F + j], w);
                d_Wc[o * F + j] = w * CS;
            } else {
                float b = d_beff[o];
                for (int k = 0; k < F; k++) b = fmaf(d_Weff[o * F + k], bk[k], b);
                d_bc[o] = b * CS;
            }
        }
    } else {
        int i = (blockIdx.x - 1) * 256 + tid;
        int stride = (gridDim.x - 1) * 256;
        float* af = (float*)d_agg4;
        for (int k = i; k < N_NODES * FP; k += stride) af[k] = 0.f;
        for (int k = i; k < B_GRAPHS * FP; k += stride) d_g[k] = 0.f;
    }
}

// ---------------- proj: 32 nodes/block, 8 threads/node x 14 outputs ----------------
__global__ __launch_bounds__(256) void proj_kernel(const float* __restrict__ x,
                                                   const float* __restrict__ Wq,
                                                   const float* __restrict__ bq,
                                                   const float* __restrict__ Wv,
                                                   const float* __restrict__ bv) {
    __shared__ __align__(16) float Wall[112 * 36];
    __shared__ float bsh[112];
    __shared__ __align__(16) float4 xs4[9][32];
    __shared__ float outS[32 * 113];
    int tid = threadIdx.x;
    int node0 = blockIdx.x * 32;

    for (int idx = tid; idx < 112 * 36; idx += 256) {
        int o = idx / 36, j = idx % 36;
        float v = 0.f;
        if (j < F && o < 105) {
            if (o < 35)      v = Wq[o * 35 + j];
            else if (o < 70) v = Wv[(o - 35) * 35 + j];
            else             v = d_Wc[(o - 70) * 35 + j];
        }
        Wall[idx] = v;
    }
    if (tid < 112) {
        float b = 0.f;
        if (tid < 35)       b = bq[tid];
        else if (tid < 70)  b = bv[tid - 35];
        else if (tid < 105) b = d_bc[tid - 70];
        bsh[tid] = b;
    }
    {
        float* xsf = (float*)xs4;
        for (int idx = tid; idx < 32 * 35; idx += 256) {
            int n = idx / 35, j = idx % 35;
            float v = (node0 + n < N_NODES) ? x[node0 * 35 + idx] : 0.f;
            xsf[(j >> 2) * 128 + n * 4 + (j & 3)] = v;
        }
        if (tid < 32) xsf[8 * 128 + tid * 4 + 3] = 0.f;
    }
    __syncthreads();

    int c = tid >> 5;
    int n = tid & 31;
    float4 xv[9];
#pragma unroll
    for (int j4 = 0; j4 < 9; j4++) xv[j4] = xs4[j4][n];
    int o0 = c * 14;
    float acc[14];
#pragma unroll
    for (int k = 0; k < 14; k++) acc[k] = bsh[o0 + k];
#pragma unroll
    for (int j4 = 0; j4 < 9; j4++) {
        float4 xq = xv[j4];
#pragma unroll
        for (int k = 0; k < 14; k++) {
            const float4 wv = *(const float4*)&Wall[(o0 + k) * 36 + j4 * 4];
            acc[k] = fmaf(wv.x, xq.x, acc[k]);
            acc[k] = fmaf(wv.y, xq.y, acc[k]);
            acc[k] = fmaf(wv.z, xq.z, acc[k]);
            acc[k] = fmaf(wv.w, xq.w, acc[k]);
        }
    }
#pragma unroll
    for (int k = 0; k < 14; k++) outS[n * 113 + o0 + k] = acc[k];
    __syncthreads();

    // Kn bf16 (queries); pad nodes -> 0
    for (int idx = tid; idx < 32 * 24; idx += 256) {
        int nn = idx / 24, wd = idx % 24;
        int real = (node0 + nn < N_NODES);
        int f0 = 2 * wd;
        float v0 = (real && f0 < 35)     ? outS[nn * 113 + 70 + f0]     : 0.f;
        float v1 = (real && f0 + 1 < 35) ? outS[nn * 113 + 70 + f0 + 1] : 0.f;
        d_Kn32[(node0 + nn) * 24 + wd] = packbf(v1, v0);
    }
    // Qk bf16 (keys); pad -> 0
    for (int idx = tid; idx < 32 * 24; idx += 256) {
        int nn = idx / 24, wd = idx % 24;
        int real = (node0 + nn < N_NODES);
        int f0 = 2 * wd;
        float v0 = (real && f0 < 35)     ? outS[nn * 113 + f0]     : 0.f;
        float v1 = (real && f0 + 1 < 35) ? outS[nn * 113 + f0 + 1] : 0.f;
        d_Qk32[(node0 + nn) * 24 + wd] = packbf(v1, v0);
    }
    // V^T bf16; row 35 = ones for real nodes, 0 for pad (kills pad-key contributions)
    for (int idx = tid; idx < 36 * 32; idx += 256) {
        int f = idx >> 5, nn = idx & 31;
        int real = (node0 + nn < N_NODES);
        float v = real ? ((f < 35) ? outS[nn * 113 + 35 + f] : 1.0f) : 0.f;
        d_VtT[f * QPAD + node0 + nn] = __bfloat16_as_ushort(__float2bfloat16(v));
    }
    // Vex exact f32
    for (int idx = tid; idx < 32 * 40; idx += 256) {
        int nn = idx / 40, f = idx % 40;
        int real = (node0 + nn < N_NODES);
        d_Vex[(node0 + nn) * 40 + f] = (real && f < 35) ? outS[nn * 113 + 35 + f] : 0.f;
    }
}

// ---------------- bf16 flash attention: 256 q/CTA, 32 q/warp, 64-key tiles ----------------
// 6 key-splits (282 CTAs) + reg cap -> 2 CTAs/SM for latency hiding.
__global__ __launch_bounds__(256, 2) void attn_kernel() {
    __shared__ __align__(16) uint32_t Ks[2][KT * 28];  // keys [64][56] bf16
    __shared__ __align__(16) uint32_t Vs[2][40 * 36];  // V^T [40][72] bf16

    int tid = threadIdx.x;
    int w = tid >> 5, lane = tid & 31;
    int gid = lane >> 2, tig = lane & 3;
    int qbase = blockIdx.x * 256 + w * 32;
    int split = blockIdx.y;
    int t0 = split * SPLIT_TILES;
    int tend = t0 + SPLIT_TILES;
    if (tend > NTILES) tend = NTILES;

    uint32_t A[2][3][4];
#pragma unroll
    for (int h = 0; h < 2; h++)
#pragma unroll
        for (int kc = 0; kc < 3; kc++) {
            int r0 = qbase + h * 16 + gid;
            A[h][kc][0] = d_Kn32[r0 * 24 + 8 * kc + tig];
            A[h][kc][1] = d_Kn32[(r0 + 8) * 24 + 8 * kc + tig];
            A[h][kc][2] = d_Kn32[r0 * 24 + 8 * kc + tig + 4];
            A[h][kc][3] = d_Kn32[(r0 + 8) * 24 + 8 * kc + tig + 4];
        }
    float O[2][5][4];
#pragma unroll
    for (int h = 0; h < 2; h++)
#pragma unroll
        for (int nt = 0; nt < 5; nt++)
#pragma unroll
            for (int r = 0; r < 4; r++) O[h][nt][r] = 0.f;

    uint32_t ksb = (uint32_t)__cvta_generic_to_shared(&Ks[0][0]);
    uint32_t vsb = (uint32_t)__cvta_generic_to_shared(&Vs[0][0]);

    {
        int k0 = t0 * KT;
        for (int i = tid; i < 704; i += 256) {
            if (i < 384) {
                int r = i / 6, ch = i % 6;
                CPA16(ksb + r * 112 + ch * 16,
                      (const char*)d_Qk32 + (size_t)(k0 + r) * 96 + ch * 16);
            } else {
                int j = i - 384; int r = j >> 3, ch = j & 7;
                CPA16(vsb + r * 144 + ch * 16,
                      (const char*)d_VtT + ((size_t)r * QPAD + k0) * 2 + ch * 16);
            }
        }
    }
    CPA_COMMIT();

    for (int t = t0; t < tend; t++) {
        int cur = (t - t0) & 1;
        if (t + 1 < tend) {
            int nb = cur ^ 1;
            int k0 = (t + 1) * KT;
            for (int i = tid; i < 704; i += 256) {
                if (i < 384) {
                    int r = i / 6, ch = i % 6;
                    CPA16(ksb + nb * 7168 + r * 112 + ch * 16,
                          (const char*)d_Qk32 + (size_t)(k0 + r) * 96 + ch * 16);
                } else {
                    int j = i - 384; int r = j >> 3, ch = j & 7;
                    CPA16(vsb + nb * 5760 + r * 144 + ch * 16,
                          (const char*)d_VtT + ((size_t)r * QPAD + k0) * 2 + ch * 16);
                }
            }
        }
        CPA_COMMIT();
        CPA_WAIT1();
        __syncthreads();

        const uint32_t* K_ = Ks[cur];
        const uint32_t* V_ = Vs[cur];

        // two nt-chunks of 4 (keys 32c..32c+31); shared fragments feed both halves
#pragma unroll
        for (int c = 0; c < 2; c++) {
            float S[2][4][4];
#pragma unroll
            for (int h = 0; h < 2; h++)
#pragma unroll
                for (int n4 = 0; n4 < 4; n4++)
#pragma unroll
                    for (int r = 0; r < 4; r++) S[h][n4][r] = 0.f;
            // ---- S chunk: Kn(2x16x48) @ keys^T ----
#pragma unroll
            for (int kc = 0; kc < 3; kc++) {
#pragma unroll
                for (int n4 = 0; n4 < 4; n4++) {
                    int nt = 4 * c + n4;
                    uint32_t b0 = K_[(nt * 8 + gid) * 28 + 8 * kc + tig];
                    uint32_t b1 = K_[(nt * 8 + gid) * 28 + 8 * kc + tig + 4];
                    MMA_BF16(S[0][n4][0], S[0][n4][1], S[0][n4][2], S[0][n4][3],
                             A[0][kc][0], A[0][kc][1], A[0][kc][2], A[0][kc][3], b0, b1);
                    MMA_BF16(S[1][n4][0], S[1][n4][1], S[1][n4][2], S[1][n4][3],
                             A[1][kc][0], A[1][kc][1], A[1][kc][2], A[1][kc][3], b0, b1);
                }
            }
            // ---- exp2 + pack P fragments ----
            uint32_t aP[2][2][4];
#pragma unroll
            for (int h = 0; h < 2; h++)
#pragma unroll
                for (int n4 = 0; n4 < 4; n4++)
#pragma unroll
                    for (int r = 0; r < 4; r++) S[h][n4][r] = ex2f(S[h][n4][r]);
#pragma unroll
            for (int h = 0; h < 2; h++)
#pragma unroll
                for (int ks = 0; ks < 2; ks++) {
                    aP[h][ks][0] = packbf(S[h][2 * ks][1],     S[h][2 * ks][0]);
                    aP[h][ks][1] = packbf(S[h][2 * ks][3],     S[h][2 * ks][2]);
                    aP[h][ks][2] = packbf(S[h][2 * ks + 1][1], S[h][2 * ks + 1][0]);
                    aP[h][ks][3] = packbf(S[h][2 * ks + 1][3], S[h][2 * ks + 1][2]);
                }
            // ---- O += P chunk @ V ----
#pragma unroll
            for (int ks = 0; ks < 2; ks++) {
                int kc = 2 * c + ks;
#pragma unroll
                for (int nt = 0; nt < 5; nt++) {
                    uint32_t b0 = V_[(nt * 8 + gid) * 36 + 8 * kc + tig];
                    uint32_t b1 = V_[(nt * 8 + gid) * 36 + 8 * kc + tig + 4];
                    MMA_BF16(O[0][nt][0], O[0][nt][1], O[0][nt][2], O[0][nt][3],
                             aP[0][ks][0], aP[0][ks][1], aP[0][ks][2], aP[0][ks][3], b0, b1);
                    MMA_BF16(O[1][nt][0], O[1][nt][1], O[1][nt][2], O[1][nt][3],
                             aP[1][ks][0], aP[1][ks][1], aP[1][ks][2], aP[1][ks][3], b0, b1);
                }
            }
        }
        __syncthreads();
    }

    float* Op = d_Opart[split];
#pragma unroll
    for (int h = 0; h < 2; h++) {
        int q0r = qbase + h * 16 + gid, q1r = q0r + 8;
#pragma unroll
        for (int nt = 0; nt < 5; nt++) {
            *(float2*)&Op[q0r * 40 + nt * 8 + 2 * tig] = make_float2(O[h][nt][0], O[h][nt][1]);
            *(float2*)&Op[q1r * 40 + nt * 8 + 2 * tig] = make_float2(O[h][nt][2], O[h][nt][3]);
        }
    }
}

// ---------------- merge: h = relu(O/l + V); elem 35 = 1.0 (degree carrier) ----------------
__global__ void merge_kernel() {
    int i = blockIdx.x * blockDim.x + threadIdx.x;
    if (i >= N_NODES * FP) return;
    int q = i / FP, f = i - q * FP;
    float r;
    if (f == 35) {
        r = 1.0f;
    } else {
        float O = 0.f, l = 0.f;
#pragma unroll
        for (int s = 0; s < NSPLIT; s++) {
            O += d_Opart[s][q * 40 + f];
            l += d_Opart[s][q * 40 + 35];
        }
        float v = d_Vex[q * 40 + f];
        r = fmaxf(fmaf(O, 1.0f / l, v), 0.f);
    }
    ((float*)d_h4)[i] = r;
}

// ---------------- SAGE scatter: thread-per-edge, v4 reductions (deg rides elem 35) ----------------
__global__ void scatter_kernel(const int* __restrict__ ei) {
    int e = blockIdx.x * blockDim.x + threadIdx.x;
    if (e >= E_EDGES) return;
    int is64 = d_is64;
    int src = is64 ? ei[2 * e] : ei[e];
    int dst = is64 ? ei[2 * (E_EDGES + e)] : ei[E_EDGES + e];
    const float4* hs = d_h4 + src * 9;
    float4* ag = d_agg4 + dst * 9;
#pragma unroll
    for (int i = 0; i < 9; i++) red4(ag + i, hs[i]);
}

// ---------------- SAGE combine + fused global max pool ----------------
__global__ __launch_bounds__(128) void sage_kernel(const float* __restrict__ Wll,
                                                   const float* __restrict__ bll,
                                                   const float* __restrict__ Wlr,
                                                   const int* __restrict__ bat) {
    __shared__ float Wl_s[F * F], Wr_s[F * F], bl_s[F];
    __shared__ float hs[F][33], as[F][33];
    __shared__ float rd[32];
    __shared__ int bs[32];
    int tid = threadIdx.x;
    int n0 = blockIdx.x * 32;
    int is64 = d_is64;
    const float* hf = (const float*)d_h4;
    const float* af = (const float*)d_agg4;
    for (int w = tid; w < F * F; w += 128) {
        Wl_s[w] = Wll[w];
        Wr_s[w] = Wlr[w];
    }
    if (tid < F) bl_s[tid] = bll[tid];
    if (tid < 32) {
        rd[tid] = 1.0f / fmaxf(af[(n0 + tid) * FP + 35], 1.0f);
        int node = n0 + tid;
        bs[tid] = is64 ? bat[2 * node] : bat[node];
    }
    for (int w = tid; w < 32 * F; w += 128) {
        int n = w / F, j = w % F;
        hs[j][n] = hf[(n0 + n) * FP + j];
        as[j][n] = af[(n0 + n) * FP + j];
    }
    __syncthreads();
    for (int w = tid; w < 32 * F; w += 128) {
        int n = w & 31, o = w >> 5;
        float a1 = 0.f, a2 = 0.f;
#pragma unroll
        for (int j = 0; j < F; j++) {
            a1 = fmaf(as[j][n], Wl_s[o * F + j], a1);
            a2 = fmaf(hs[j][n], Wr_s[o * F + j], a2);
        }
        float r = fmaf(a1, rd[n], bl_s[o]) + a2;
        r = fmaxf(r, 0.f);
        atomicMax((int*)&d_g[bs[n] * FP + o], __float_as_int(r));
    }
}

// ---------------- MLP head ----------------
__global__ __launch_bounds__(128) void mlp1_kernel(const float* __restrict__ Wg1,
                                                   const float* __restrict__ bg1) {
    __shared__ float gs[F][64];
    int tid = threadIdx.x;
    for (int w = tid; w < 64 * F; w += 128) {
        int b = w / F, d = w % F;
        gs[d][b] = d_g[b * FP + d];
    }
    __syncthreads();
    int j = blockIdx.x * 2 + (tid >> 6);
    int b = tid & 63;
    float acc = 0.f;
#pragma unroll
    for (int d = 0; d < F; d++) acc = fmaf(gs[d][b], __ldg(&Wg1[j * F + d]), acc);
    d_g1[b * H1 + j] = fmaxf(acc + bg1[j], 0.f);
}

__global__ void mlp2_kernel(const float* __restrict__ Wg2, const float* __restrict__ bg2) {
    int wid = (blockIdx.x * blockDim.x + threadIdx.x) >> 5;
    int lane = threadIdx.x & 31;
    if (wid >= B_GRAPHS * H2) return;
    int b = wid >> 7, j = wid & 127;
    float acc = 0.f;
    for (int d = lane; d < H1; d += 32)
        acc = fmaf(d_g1[b * H1 + d], Wg2[j * H1 + d], acc);
#pragma unroll
    for (int off = 16; off; off >>= 1) acc += __shfl_xor_sync(0xffffffffu, acc, off);
    if (lane == 0) d_g2[b * H2 + j] = acc + bg2[j];
}

__global__ void out_kernel(const float* __restrict__ Wo, const float* __restrict__ bo,
                           float* __restrict__ out) {
    int b = threadIdx.x;
    if (b < B_GRAPHS) {
        float acc = 0.f;
#pragma unroll
        for (int d = 0; d < H2; d++) acc = fmaf(d_g2[b * H2 + d], Wo[d], acc);
        out[b] = acc + bo[0];
    }
}

extern "C" void kernel_launch(void* const* d_in, const int* in_sizes, int n_in,
                              void* d_out, int out_size) {
    const float* x   = (const float*)d_in[0];
    const int*   ei  = (const int*)d_in[1];
    const int*   bat = (const int*)d_in[2];
    const float* Wq  = (const float*)d_in[3];
    const float* bq  = (const float*)d_in[4];
    const float* Wk  = (const float*)d_in[5];
    const float* bk  = (const float*)d_in[6];
    const float* Wv  = (const float*)d_in[7];
    const float* bv  = (const float*)d_in[8];
    const float* W3  = (const float*)d_in[9];
    const float* b3  = (const float*)d_in[10];
    const float* W5  = (const float*)d_in[11];
    const float* b5  = (const float*)d_in[12];
    const float* Wl  = (const float*)d_in[13];
    const float* bl  = (const float*)d_in[14];
    const float* Wll = (const float*)d_in[15];
    const float* bll = (const float*)d_in[16];
    const float* Wlr = (const float*)d_in[17];
    const float* Wg1 = (const float*)d_in[18];
    const float* bg1 = (const float*)d_in[19];
    const float* Wg2 = (const float*)d_in[20];
    const float* bg2 = (const float*)d_in[21];
    const float* Wo  = (const float*)d_in[22];
    const float* bo  = (const float*)d_in[23];
    float* out = (float*)d_out;

    setup_kernel<<<64, 256>>>(ei, Wl, W3, W5, b3, b5, bl, Wk, bk);
    proj_kernel<<<QPAD / 32, 256>>>(x, Wq, bq, Wv, bv);
    attn_kernel<<<dim3(47, NSPLIT), 256>>>();
    merge_kernel<<<(N_NODES * FP + 255) / 256, 256>>>();
    scatter_kernel<<<(E_EDGES + 255) / 256, 256>>>(ei);
    sage_kernel<<<N_NODES / 32, 128>>>(Wll, bll, Wlr, bat);
    mlp1_kernel<<<H1 / 2, 128>>>(Wg1, bg1);
    mlp2_kernel<<<B_GRAPHS * H2 / 4, 128>>>(Wg2, bg2);
    out_kernel<<<1, 64>>>(Wo, bo, out);
}

// round 15
// speedup vs baseline: 1.1480x; 1.0343x over previous
#include <cuda_runtime.h>
#include <cuda_bf16.h>
#include <math.h>
#include <stdint.h>

#define N_NODES 12000
#define F 35
#define FP 36
#define QPAD 12032
#define NSPLIT 6
#define SPLIT_TILES 32
#define KT 64
#define NTILES 188          // 188 * 64 = 12032 padded keys
#define E_EDGES 192000
#define B_GRAPHS 64
#define H1 1500
#define H2 128

#define KTILE_W (KT * 32)   // 2048 words per K tile
#define VTILE_W (40 * 32)   // 1280 words per V tile
#define KBYTES (KTILE_W * 4)
#define VBYTES (VTILE_W * 4)

// ---------------- scratch ----------------
__device__ __align__(16) uint32_t d_Kn32[QPAD * 24];          // queries bf16 [row][48]
__device__ __align__(128) uint32_t d_QkB[NTILES * KTILE_W];   // keys bf16, tile-blocked + rotated
__device__ __align__(128) uint32_t d_VtB[NTILES * VTILE_W];   // V^T bf16, tile-blocked + rotated
__device__ float d_Vex[QPAD * 40];
__device__ float d_Opart[NSPLIT][QPAD * 40];
__device__ float4 d_h4[N_NODES * 9];    // h, 36-stride; elem35 = 1.0 (deg carrier)
__device__ float4 d_agg4[N_NODES * 9];  // agg; elem35 accumulates degree
__device__ float d_Weff[F * F];
__device__ float d_beff[F];
__device__ float d_Wc[F * F];
__device__ float d_bc[F];
__device__ float d_g[B_GRAPHS * FP];
__device__ float d_g1[B_GRAPHS * H1];
__device__ float d_g2[B_GRAPHS * H2];
__device__ int d_is64;

__device__ __forceinline__ float ex2f(float x) {
    float r;
    asm("ex2.approx.f32 %0, %1;" : "=f"(r) : "f"(x));
    return r;
}
__device__ __forceinline__ uint32_t packbf(float hi, float lo) {
    uint32_t r;
    asm("cvt.rn.bf16x2.f32 %0, %1, %2;" : "=r"(r) : "f"(hi), "f"(lo));
    return r;
}
#define MMA_BF16(d0, d1, d2, d3, a0, a1, a2, a3, b0, b1)                                   \
    asm volatile(                                                                          \
        "mma.sync.aligned.m16n8k16.row.col.f32.bf16.bf16.f32 "                             \
        "{%0,%1,%2,%3},{%4,%5,%6,%7},{%8,%9},{%0,%1,%2,%3};"                               \
        : "+f"(d0), "+f"(d1), "+f"(d2), "+f"(d3)                                           \
        : "r"(a0), "r"(a1), "r"(a2), "r"(a3), "r"(b0), "r"(b1))

#define MBAR_INIT(addr, cnt) \
    asm volatile("mbarrier.init.shared.b64 [%0], %1;" :: "r"(addr), "r"(cnt) : "memory")
#define MBAR_EXPECT_TX(addr, bytes) \
    asm volatile("mbarrier.arrive.expect_tx.shared.b64 _, [%0], %1;" :: "r"(addr), "r"(bytes) : "memory")
#define BULK_G2S(dst, src, size, mbar)                                                     \
    asm volatile("cp.async.bulk.shared::cta.global.mbarrier::complete_tx::bytes "          \
                 "[%0], [%1], %2, [%3];"                                                   \
                 :: "r"(dst), "l"(src), "r"(size), "r"(mbar) : "memory")
#define MBAR_WAIT(addr, parity) do {                                                       \
    asm volatile(                                                                          \
        "{\n\t.reg .pred P1;\n\t"                                                          \
        "WAIT_LOOP_%=:\n\t"                                                                \
        "mbarrier.try_wait.parity.acquire.cta.shared::cta.b64 P1, [%0], %1, 0x989680;\n\t" \
        "@P1 bra.uni WAIT_DONE_%=;\n\t"                                                    \
        "bra.uni WAIT_LOOP_%=;\n\t"                                                        \
        "WAIT_DONE_%=:\n\t}"                                                               \
        :: "r"(addr), "r"(parity) : "memory");                                             \
} while (0)

__device__ __forceinline__ void red4(float4* p, float4 v) {
    asm volatile("red.global.add.v4.f32 [%0], {%1,%2,%3,%4};"
                 :: "l"(p), "f"(v.x), "f"(v.y), "f"(v.z), "f"(v.w) : "memory");
}

// ---------------- setup: detect + pre1 + pre2 (block 0), zero (blocks 1+) ----------------
__global__ void setup_kernel(const int* __restrict__ ei,
                             const float* __restrict__ Wl, const float* __restrict__ W3,
                             const float* __restrict__ W5, const float* __restrict__ b3,
                             const float* __restrict__ b5, const float* __restrict__ bl,
                             const float* __restrict__ Wk, const float* __restrict__ bk) {
    int tid = threadIdx.x;
    if (blockIdx.x == 0) {
        if (tid == 0) {
            int all0 = 1;
            for (int i = 0; i < 16; i++)
                if (ei[2 * i + 1] != 0) all0 = 0;
            d_is64 = all0;
        }
        for (int idx = tid; idx < F * 36; idx += 256) {
            int o = idx / 36, k = idx % 36;
            if (k < F) {
                float w = Wl[o * 105 + 70 + k];
                for (int m = 0; m < F; m++) {
                    w = fmaf(Wl[o * 105 + m],      W3[(m * F + k) * 3 + 1], w);
                    w = fmaf(Wl[o * 105 + 35 + m], W5[(m * F + k) * 5 + 2], w);
                }
                d_Weff[o * F + k] = w;
            } else {
                float be = bl[o];
                for (int m = 0; m < F; m++) {
                    be = fmaf(Wl[o * 105 + m],      b3[m], be);
                    be = fmaf(Wl[o * 105 + 35 + m], b5[m], be);
                }
                d_beff[o] = be;
            }
        }
        __syncthreads();
        const float CS = 1.4426950408889634f / sqrtf((float)F);
        for (int idx = tid; idx < F * 36; idx += 256) {
            int o = idx / 36, j = idx % 36;
            if (j < F) {
                float w = 0.f;
                for (int k = 0; k < F; k++) w = fmaf(d_Weff[o * F + k], Wk[k * F + j], w);
                d_Wc[o * F + j] = w * CS;
            } else {
                float b = d_beff[o];
                for (int k = 0; k < F; k++) b = fmaf(d_Weff[o * F + k], bk[k], b);
                d_bc[o] = b * CS;
            }
        }
    } else {
        int i = (blockIdx.x - 1) * 256 + tid;
        int stride = (gridDim.x - 1) * 256;
        float* af = (float*)d_agg4;
        for (int k = i; k < N_NODES * FP; k += stride) af[k] = 0.f;
        for (int k = i; k < B_GRAPHS * FP; k += stride) d_g[k] = 0.f;
    }
}

// ---------------- proj: 32 nodes/block, 8 threads/node x 14 outputs ----------------
__global__ __launch_bounds__(256) void proj_kernel(const float* __restrict__ x,
                                                   const float* __restrict__ Wq,
                                                   const float* __restrict__ bq,
                                                   const float* __restrict__ Wv,
                                                   const float* __restrict__ bv) {
    __shared__ __align__(16) float Wall[112 * 36];
    __shared__ float bsh[112];
    __shared__ __align__(16) float4 xs4[9][32];
    __shared__ float outS[32 * 113];
    int tid = threadIdx.x;
    int node0 = blockIdx.x * 32;

    for (int idx = tid; idx < 112 * 36; idx += 256) {
        int o = idx / 36, j = idx % 36;
        float v = 0.f;
        if (j < F && o < 105) {
            if (o < 35)      v = Wq[o * 35 + j];
            else if (o < 70) v = Wv[(o - 35) * 35 + j];
            else             v = d_Wc[(o - 70) * 35 + j];
        }
        Wall[idx] = v;
    }
    if (tid < 112) {
        float b = 0.f;
        if (tid < 35)       b = bq[tid];
        else if (tid < 70)  b = bv[tid - 35];
        else if (tid < 105) b = d_bc[tid - 70];
        bsh[tid] = b;
    }
    {
        float* xsf = (float*)xs4;
        for (int idx = tid; idx < 32 * 35; idx += 256) {
            int n = idx / 35, j = idx % 35;
            float v = (node0 + n < N_NODES) ? x[node0 * 35 + idx] : 0.f;
            xsf[(j >> 2) * 128 + n * 4 + (j & 3)] = v;
        }
        if (tid < 32) xsf[8 * 128 + tid * 4 + 3] = 0.f;
    }
    __syncthreads();

    int c = tid >> 5;
    int n = tid & 31;
    float4 xv[9];
#pragma unroll
    for (int j4 = 0; j4 < 9; j4++) xv[j4] = xs4[j4][n];
    int o0 = c * 14;
    float acc[14];
#pragma unroll
    for (int k = 0; k < 14; k++) acc[k] = bsh[o0 + k];
#pragma unroll
    for (int j4 = 0; j4 < 9; j4++) {
        float4 xq = xv[j4];
#pragma unroll
        for (int k = 0; k < 14; k++) {
            const float4 wv = *(const float4*)&Wall[(o0 + k) * 36 + j4 * 4];
            acc[k] = fmaf(wv.x, xq.x, acc[k]);
            acc[k] = fmaf(wv.y, xq.y, acc[k]);
            acc[k] = fmaf(wv.z, xq.z, acc[k]);
            acc[k] = fmaf(wv.w, xq.w, acc[k]);
        }
    }
#pragma unroll
    for (int k = 0; k < 14; k++) outS[n * 113 + o0 + k] = acc[k];
    __syncthreads();

    int tb = node0 >> 6;          // tile index
    int rbase = node0 & 63;       // row base within tile (0 or 32)

    // Kn bf16 (queries), row-major 24 words — A fragments load straight from gmem
    for (int idx = tid; idx < 32 * 24; idx += 256) {
        int nn = idx / 24, wd = idx % 24;
        int real = (node0 + nn < N_NODES);
        int f0 = 2 * wd;
        float v0 = (real && f0 < 35)     ? outS[nn * 113 + 70 + f0]     : 0.f;
        float v1 = (real && f0 + 1 < 35) ? outS[nn * 113 + 70 + f0 + 1] : 0.f;
        d_Kn32[(node0 + nn) * 24 + wd] = packbf(v1, v0);
    }
    // Keys, tile-blocked [tile][64][32w], row rotated by 4*r (mod 32); pad words/nodes -> 0
    for (int idx = tid; idx < 32 * 32; idx += 256) {
        int nn = idx >> 5, p = idx & 31;
        int r = rbase + nn;
        int wd = (p - 4 * r) & 31;
        int f0 = 2 * wd;
        int real = (node0 + nn < N_NODES);
        float v0 = (real && f0 < 35)     ? outS[nn * 113 + f0]     : 0.f;
        float v1 = (real && f0 + 1 < 35) ? outS[nn * 113 + f0 + 1] : 0.f;
        d_QkB[tb * KTILE_W + r * 32 + p] = packbf(v1, v0);
    }
    // V^T, tile-blocked [tile][40][32w], row f rotated by 4*f; row35 = ones, pads 0.
    // This block owns 16 of the 32 words of each row (its 32-node slice).
    {
        int g0 = rbase >> 1;
        for (int idx = tid; idx < 40 * 16; idx += 256) {
            int f = idx >> 4, wq = idx & 15;
            int wd = g0 + wq;
            int p = (wd + 4 * f) & 31;
            int n0l = 2 * wq;
            float v0 = 0.f, v1 = 0.f;
            if (node0 + n0l < N_NODES)
                v0 = (f < 35) ? outS[n0l * 113 + 35 + f] : ((f == 35) ? 1.0f : 0.f);
            if (node0 + n0l + 1 < N_NODES)
                v1 = (f < 35) ? outS[(n0l + 1) * 113 + 35 + f] : ((f == 35) ? 1.0f : 0.f);
            d_VtB[tb * VTILE_W + f * 32 + p] = packbf(v1, v0);
        }
    }
    // Vex exact f32
    for (int idx = tid; idx < 32 * 40; idx += 256) {
        int nn = idx / 40, f = idx % 40;
        int real = (node0 + nn < N_NODES);
        d_Vex[(node0 + nn) * 40 + f] = (real && f < 35) ? outS[nn * 113 + 35 + f] : 0.f;
    }
}

// ---------------- bf16 flash attention: 256 q/CTA, 32 q/warp, 64-key tiles ----------------
// Staging via cp.async.bulk (2 ops/tile) + mbarrier; rotated layouts are LDS conflict-free.
__global__ __launch_bounds__(256, 2) void attn_kernel() {
    __shared__ __align__(128) uint32_t Ks[2][KTILE_W];
    __shared__ __align__(128) uint32_t Vs[2][VTILE_W];
    __shared__ __align__(8) uint64_t mbar[2];

    int tid = threadIdx.x;
    int w = tid >> 5, lane = tid & 31;
    int gid = lane >> 2, tig = lane & 3;
    int qbase = blockIdx.x * 256 + w * 32;
    int split = blockIdx.y;
    int t0 = split * SPLIT_TILES;
    int tend = t0 + SPLIT_TILES;
    if (tend > NTILES) tend = NTILES;

    uint32_t mb0 = (uint32_t)__cvta_generic_to_shared(&mbar[0]);
    uint32_t mb1 = (uint32_t)__cvta_generic_to_shared(&mbar[1]);
    uint32_t ks0 = (uint32_t)__cvta_generic_to_shared(&Ks[0][0]);
    uint32_t vs0 = (uint32_t)__cvta_generic_to_shared(&Vs[0][0]);

    if (tid == 0) {
        MBAR_INIT(mb0, 1);
        MBAR_INIT(mb1, 1);
    }
    __syncthreads();

    uint32_t A[2][3][4];
#pragma unroll
    for (int h = 0; h < 2; h++)
#pragma unroll
        for (int kc = 0; kc < 3; kc++) {
            int r0 = qbase + h * 16 + gid;
            A[h][kc][0] = d_Kn32[r0 * 24 + 8 * kc + tig];
            A[h][kc][1] = d_Kn32[(r0 + 8) * 24 + 8 * kc + tig];
            A[h][kc][2] = d_Kn32[r0 * 24 + 8 * kc + tig + 4];
            A[h][kc][3] = d_Kn32[(r0 + 8) * 24 + 8 * kc + tig + 4];
        }
    float O[2][5][4];
#pragma unroll
    for (int h = 0; h < 2; h++)
#pragma unroll
        for (int nt = 0; nt < 5; nt++)
#pragma unroll
            for (int r = 0; r < 4; r++) O[h][nt][r] = 0.f;

    int rot = tig + 4 * gid;  // rotation offset: conflict-free permutation

    // prefetch tile t0 into buf 0
    if (tid == 0) {
        MBAR_EXPECT_TX(mb0, KBYTES + VBYTES);
        BULK_G2S(ks0, (const char*)(d_QkB + (size_t)t0 * KTILE_W), KBYTES, mb0);
        BULK_G2S(vs0, (const char*)(d_VtB + (size_t)t0 * VTILE_W), VBYTES, mb0);
    }

    int ph0 = 0, ph1 = 0;
    for (int t = t0; t < tend; t++) {
        int cur = (t - t0) & 1;
        if (t + 1 < tend && tid == 0) {
            int nb = cur ^ 1;
            uint32_t mbn = nb ? mb1 : mb0;
            MBAR_EXPECT_TX(mbn, KBYTES + VBYTES);
            BULK_G2S(ks0 + nb * KBYTES, (const char*)(d_QkB + (size_t)(t + 1) * KTILE_W),
                     KBYTES, mbn);
            BULK_G2S(vs0 + nb * VBYTES, (const char*)(d_VtB + (size_t)(t + 1) * VTILE_W),
                     VBYTES, mbn);
        }
        if (cur == 0) { MBAR_WAIT(mb0, ph0); ph0 ^= 1; }
        else          { MBAR_WAIT(mb1, ph1); ph1 ^= 1; }

        const uint32_t* K_ = Ks[cur];
        const uint32_t* V_ = Vs[cur];

        // two nt-chunks of 4 (keys 32c..32c+31); shared fragments feed both halves
#pragma unroll
        for (int c = 0; c < 2; c++) {
            float S[2][4][4];
#pragma unroll
            for (int h = 0; h < 2; h++)
#pragma unroll
                for (int n4 = 0; n4 < 4; n4++)
#pragma unroll
                    for (int r = 0; r < 4; r++) S[h][n4][r] = 0.f;
            // ---- S chunk: Kn(2x16x48) @ keys^T ----
#pragma unroll
            for (int kc = 0; kc < 3; kc++) {
#pragma unroll
                for (int n4 = 0; n4 < 4; n4++) {
                    int nt = 4 * c + n4;
                    const uint32_t* row = K_ + (nt * 8 + gid) * 32;
                    uint32_t b0 = row[(8 * kc + rot) & 31];
                    uint32_t b1 = row[(8 * kc + 4 + rot) & 31];
                    MMA_BF16(S[0][n4][0], S[0][n4][1], S[0][n4][2], S[0][n4][3],
                             A[0][kc][0], A[0][kc][1], A[0][kc][2], A[0][kc][3], b0, b1);
                    MMA_BF16(S[1][n4][0], S[1][n4][1], S[1][n4][2], S[1][n4][3],
                             A[1][kc][0], A[1][kc][1], A[1][kc][2], A[1][kc][3], b0, b1);
                }
            }
            // ---- exp2 + pack P fragments ----
            uint32_t aP[2][2][4];
#pragma unroll
            for (int h = 0; h < 2; h++)
#pragma unroll
                for (int n4 = 0; n4 < 4; n4++)
#pragma unroll
                    for (int r = 0; r < 4; r++) S[h][n4][r] = ex2f(S[h][n4][r]);
#pragma unroll
            for (int h = 0; h < 2; h++)
#pragma unroll
                for (int ks = 0; ks < 2; ks++) {
                    aP[h][ks][0] = packbf(S[h][2 * ks][1],     S[h][2 * ks][0]);
                    aP[h][ks][1] = packbf(S[h][2 * ks][3],     S[h][2 * ks][2]);
                    aP[h][ks][2] = packbf(S[h][2 * ks + 1][1], S[h][2 * ks + 1][0]);
                    aP[h][ks][3] = packbf(S[h][2 * ks + 1][3], S[h][2 * ks + 1][2]);
                }
            // ---- O += P chunk @ V ----
#pragma unroll
            for (int ks = 0; ks < 2; ks++) {
                int kc = 2 * c + ks;
#pragma unroll
                for (int nt = 0; nt < 5; nt++) {
                    const uint32_t* row = V_ + (nt * 8 + gid) * 32;
                    uint32_t b0 = row[(8 * kc + rot) & 31];
                    uint32_t b1 = row[(8 * kc + 4 + rot) & 31];
                    MMA_BF16(O[0][nt][0], O[0][nt][1], O[0][nt][2], O[0][nt][3],
                             aP[0][ks][0], aP[0][ks][1], aP[0][ks][2], aP[0][ks][3], b0, b1);
                    MMA_BF16(O[1][nt][0], O[1][nt][1], O[1][nt][2], O[1][nt][3],
                             aP[1][ks][0], aP[1][ks][1], aP[1][ks][2], aP[1][ks][3], b0, b1);
                }
            }
        }
        __syncthreads();   // all consumers done with buffer before producer refills it
    }

    float* Op = d_Opart[split];
#pragma unroll
    for (int h = 0; h < 2; h++) {
        int q0r = qbase + h * 16 + gid, q1r = q0r + 8;
#pragma unroll
        for (int nt = 0; nt < 5; nt++) {
            *(float2*)&Op[q0r * 40 + nt * 8 + 2 * tig] = make_float2(O[h][nt][0], O[h][nt][1]);
            *(float2*)&Op[q1r * 40 + nt * 8 + 2 * tig] = make_float2(O[h][nt][2], O[h][nt][3]);
        }
    }
}

// ---------------- merge: h = relu(O/l + V); elem 35 = 1.0 (degree carrier) ----------------
__global__ void merge_kernel() {
    int i = blockIdx.x * blockDim.x + threadIdx.x;
    if (i >= N_NODES * FP) return;
    int q = i / FP, f = i - q * FP;
    float r;
    if (f == 35) {
        r = 1.0f;
    } else {
        float O = 0.f, l = 0.f;
#pragma unroll
        for (int s = 0; s < NSPLIT; s++) {
            O += d_Opart[s][q * 40 + f];
            l += d_Opart[s][q * 40 + 35];
        }
        float v = d_Vex[q * 40 + f];
        r = fmaxf(fmaf(O, 1.0f / l, v), 0.f);
    }
    ((float*)d_h4)[i] = r;
}

// ---------------- SAGE scatter: thread-per-edge, v4 reductions (deg rides elem 35) ----------------
__global__ void scatter_kernel(const int* __restrict__ ei) {
    int e = blockIdx.x * blockDim.x + threadIdx.x;
    if (e >= E_EDGES) return;
    int is64 = d_is64;
    int src = is64 ? ei[2 * e] : ei[e];
    int dst = is64 ? ei[2 * (E_EDGES + e)] : ei[E_EDGES + e];
    const float4* hs = d_h4 + src * 9;
    float4* ag = d_agg4 + dst * 9;
#pragma unroll
    for (int i = 0; i < 9; i++) red4(ag + i, hs[i]);
}

// ---------------- SAGE combine + fused global max pool ----------------
__global__ __launch_bounds__(128) void sage_kernel(const float* __restrict__ Wll,
                                                   const float* __restrict__ bll,
                                                   const float* __restrict__ Wlr,
                                                   const int* __restrict__ bat) {
    __shared__ float Wl_s[F * F], Wr_s[F * F], bl_s[F];
    __shared__ float hs[F][33], as[F][33];
    __shared__ float rd[32];
    __shared__ int bs[32];
    int tid = threadIdx.x;
    int n0 = blockIdx.x * 32;
    int is64 = d_is64;
    const float* hf = (const float*)d_h4;
    const float* af = (const float*)d_agg4;
    for (int w = tid; w < F * F; w += 128) {
        Wl_s[w] = Wll[w];
        Wr_s[w] = Wlr[w];
    }
    if (tid < F) bl_s[tid] = bll[tid];
    if (tid < 32) {
        rd[tid] = 1.0f / fmaxf(af[(n0 + tid) * FP + 35], 1.0f);
        int node = n0 + tid;
        bs[tid] = is64 ? bat[2 * node] : bat[node];
    }
    for (int w = tid; w < 32 * F; w += 128) {
        int n = w / F, j = w % F;
        hs[j][n] = hf[(n0 + n) * FP + j];
        as[j][n] = af[(n0 + n) * FP + j];
    }
    __syncthreads();
    for (int w = tid; w < 32 * F; w += 128) {
        int n = w & 31, o = w >> 5;
        float a1 = 0.f, a2 = 0.f;
#pragma unroll
        for (int j = 0; j < F; j++) {
            a1 = fmaf(as[j][n], Wl_s[o * F + j], a1);
            a2 = fmaf(hs[j][n], Wr_s[o * F + j], a2);
        }
        float r = fmaf(a1, rd[n], bl_s[o]) + a2;
        r = fmaxf(r, 0.f);
        atomicMax((int*)&d_g[bs[n] * FP + o], __float_as_int(r));
    }
}

// ---------------- MLP head ----------------
__global__ __launch_bounds__(128) void mlp1_kernel(const float* __restrict__ Wg1,
                                                   const float* __restrict__ bg1) {
    __shared__ float gs[F][64];
    int tid = threadIdx.x;
    for (int w = tid; w < 64 * F; w += 128) {
        int b = w / F, d = w % F;
        gs[d][b] = d_g[b * FP + d];
    }
    __syncthreads();
    int j = blockIdx.x * 2 + (tid >> 6);
    int b = tid & 63;
    float acc = 0.f;
#pragma unroll
    for (int d = 0; d < F; d++) acc = fmaf(gs[d][b], __ldg(&Wg1[j * F + d]), acc);
    d_g1[b * H1 + j] = fmaxf(acc + bg1[j], 0.f);
}

__global__ void mlp2_kernel(const float* __restrict__ Wg2, const float* __restrict__ bg2) {
    int wid = (blockIdx.x * blockDim.x + threadIdx.x) >> 5;
    int lane = threadIdx.x & 31;
    if (wid >= B_GRAPHS * H2) return;
    int b = wid >> 7, j = wid & 127;
    float acc = 0.f;
    for (int d = lane; d < H1; d += 32)
        acc = fmaf(d_g1[b * H1 + d], Wg2[j * H1 + d], acc);
#pragma unroll
    for (int off = 16; off; off >>= 1) acc += __shfl_xor_sync(0xffffffffu, acc, off);
    if (lane == 0) d_g2[b * H2 + j] = acc + bg2[j];
}

__global__ void out_kernel(const float* __restrict__ Wo, const float* __restrict__ bo,
                           float* __restrict__ out) {
    int b = threadIdx.x;
    if (b < B_GRAPHS) {
        float acc = 0.f;
#pragma unroll
        for (int d = 0; d < H2; d++) acc = fmaf(d_g2[b * H2 + d], Wo[d], acc);
        out[b] = acc + bo[0];
    }
}

extern "C" void kernel_launch(void* const* d_in, const int* in_sizes, int n_in,
                              void* d_out, int out_size) {
    const float* x   = (const float*)d_in[0];
    const int*   ei  = (const int*)d_in[1];
    const int*   bat = (const int*)d_in[2];
    const float* Wq  = (const float*)d_in[3];
    const float* bq  = (const float*)d_in[4];
    const float* Wk  = (const float*)d_in[5];
    const float* bk  = (const float*)d_in[6];
    const float* Wv  = (const float*)d_in[7];
    const float* bv  = (const float*)d_in[8];
    const float* W3  = (const float*)d_in[9];
    const float* b3  = (const float*)d_in[10];
    const float* W5  = (const float*)d_in[11];
    const float* b5  = (const float*)d_in[12];
    const float* Wl  = (const float*)d_in[13];
    const float* bl  = (const float*)d_in[14];
    const float* Wll = (const float*)d_in[15];
    const float* bll = (const float*)d_in[16];
    const float* Wlr = (const float*)d_in[17];
    const float* Wg1 = (const float*)d_in[18];
    const float* bg1 = (const float*)d_in[19];
    const float* Wg2 = (const float*)d_in[20];
    const float* bg2 = (const float*)d_in[21];
    const float* Wo  = (const float*)d_in[22];
    const float* bo  = (const float*)d_in[23];
    float* out = (float*)d_out;

    setup_kernel<<<64, 256>>>(ei, Wl, W3, W5, b3, b5, bl, Wk, bk);
    proj_kernel<<<QPAD / 32, 256>>>(x, Wq, bq, Wv, bv);
    attn_kernel<<<dim3(47, NSPLIT), 256>>>();
    merge_kernel<<<(N_NODES * FP + 255) / 256, 256>>>();
    scatter_kernel<<<(E_EDGES + 255) / 256, 256>>>(ei);
    sage_kernel<<<N_NODES / 32, 128>>>(Wll, bll, Wlr, bat);
    mlp1_kernel<<<H1 / 2, 128>>>(Wg1, bg1);
    mlp2_kernel<<<B_GRAPHS * H2 / 4, 128>>>(Wg2, bg2);
    out_kernel<<<1, 64>>>(Wo, bo, out);
}